// round 1
// baseline (speedup 1.0000x reference)
#include <cuda_runtime.h>
#include <math.h>

#define SEQ 3072
#define DIM 1024
#define NHEAD 4
#define DHEAD 256
#define NLAYER 4
#define LN_EPS 1e-5f

// ---------------- scratch (static device arrays; no allocation) ----------------
__device__ float g_h[SEQ * DIM];
__device__ float g_Q[SEQ * DIM];
__device__ float g_K[SEQ * DIM];
__device__ float g_V[SEQ * DIM];
__device__ float g_Qh[SEQ * DIM];   // [head][s][e]
__device__ float g_Kh[SEQ * DIM];
__device__ float g_Vh[SEQ * DIM];
__device__ float g_scores[(size_t)NHEAD * SEQ * SEQ];
__device__ float g_ctx[SEQ * DIM];  // [s][head*DHEAD+e]
__device__ float g_tmp[SEQ * DIM];
__device__ float g_ffn1[SEQ * 2 * DIM];

// ---------------- generic tiled SGEMM: C = alpha*A@op(B) + bias (opt relu) ------
// A: M x K row-major (lda). B normal: K x N row-major (ldb). B trans: N x K (ldb).
// Batched over blockIdx.z with element strides. All of M%128, N%128, K%8 == 0.
template <bool TRANSB>
__global__ void __launch_bounds__(256)
gemm_kernel(const float* __restrict__ Ag, const float* __restrict__ Bg,
            const float* __restrict__ biasg, float* __restrict__ Cg,
            int M, int N, int K, int lda, int ldb, int ldc,
            long sA, long sB, long sBias, long sC,
            float alpha, int relu)
{
    const float* Ap = Ag + sA * blockIdx.z;
    const float* Bp = Bg + sB * blockIdx.z;
    const float* biasp = biasg ? (biasg + sBias * blockIdx.z) : nullptr;
    float* Cp = Cg + sC * blockIdx.z;

    __shared__ float As[8][128];
    __shared__ float Bs[8][128];

    const int tid = threadIdx.x;
    const int tx = tid & 15;        // 0..15 -> N
    const int ty = tid >> 4;        // 0..15 -> M
    const int row0 = blockIdx.y * 128;
    const int col0 = blockIdx.x * 128;

    // A tile load: 128 rows x 8 k, one float4 per thread
    const int aRow = tid >> 1;
    const int aCol = (tid & 1) * 4;
    // B normal load: 8 k-rows x 128 n, one float4 per thread
    const int bK = tid >> 5;
    const int bCol = (tid & 31) * 4;
    // B trans load: 128 n-rows x 8 k
    const int bRow = tid >> 1;
    const int bkCol = (tid & 1) * 4;

    float acc[8][8];
#pragma unroll
    for (int i = 0; i < 8; i++)
#pragma unroll
        for (int j = 0; j < 8; j++) acc[i][j] = 0.0f;

    for (int k0 = 0; k0 < K; k0 += 8) {
        float4 av = *(const float4*)(Ap + (long)(row0 + aRow) * lda + k0 + aCol);
        As[aCol + 0][aRow] = av.x;
        As[aCol + 1][aRow] = av.y;
        As[aCol + 2][aRow] = av.z;
        As[aCol + 3][aRow] = av.w;
        if (TRANSB) {
            float4 bv = *(const float4*)(Bp + (long)(col0 + bRow) * ldb + k0 + bkCol);
            Bs[bkCol + 0][bRow] = bv.x;
            Bs[bkCol + 1][bRow] = bv.y;
            Bs[bkCol + 2][bRow] = bv.z;
            Bs[bkCol + 3][bRow] = bv.w;
        } else {
            float4 bv = *(const float4*)(Bp + (long)(k0 + bK) * ldb + col0 + bCol);
            *(float4*)&Bs[bK][bCol] = bv;
        }
        __syncthreads();

#pragma unroll
        for (int kk = 0; kk < 8; kk++) {
            float a[8], b[8];
#pragma unroll
            for (int i = 0; i < 8; i++) a[i] = As[kk][ty * 8 + i];
#pragma unroll
            for (int j = 0; j < 8; j++) b[j] = Bs[kk][tx * 8 + j];
#pragma unroll
            for (int i = 0; i < 8; i++)
#pragma unroll
                for (int j = 0; j < 8; j++) acc[i][j] = fmaf(a[i], b[j], acc[i][j]);
        }
        __syncthreads();
    }

#pragma unroll
    for (int i = 0; i < 8; i++) {
        const long r = row0 + ty * 8 + i;
#pragma unroll
        for (int j = 0; j < 8; j += 4) {
            const int c = col0 + tx * 8 + j;
            float4 v;
            v.x = acc[i][j + 0] * alpha;
            v.y = acc[i][j + 1] * alpha;
            v.z = acc[i][j + 2] * alpha;
            v.w = acc[i][j + 3] * alpha;
            if (biasp) {
                v.x += biasp[c + 0];
                v.y += biasp[c + 1];
                v.z += biasp[c + 2];
                v.w += biasp[c + 3];
            }
            if (relu) {
                v.x = fmaxf(v.x, 0.0f);
                v.y = fmaxf(v.y, 0.0f);
                v.z = fmaxf(v.z, 0.0f);
                v.w = fmaxf(v.w, 0.0f);
            }
            *(float4*)(Cp + r * ldc + c) = v;
        }
    }
}

// ---------------- softmax over rows of length SEQ (block per row) --------------
__global__ void __launch_bounds__(256)
softmax_kernel(float* __restrict__ scores)
{
    const long row = blockIdx.x;
    float* p = scores + row * (long)SEQ;
    const int tid = threadIdx.x;

    float v[12];
    float mx = -1e30f;
#pragma unroll
    for (int i = 0; i < 12; i++) {
        v[i] = p[tid + i * 256];
        mx = fmaxf(mx, v[i]);
    }
    __shared__ float red[256];
    red[tid] = mx;
    __syncthreads();
    for (int s = 128; s > 0; s >>= 1) {
        if (tid < s) red[tid] = fmaxf(red[tid], red[tid + s]);
        __syncthreads();
    }
    mx = red[0];
    __syncthreads();

    float sum = 0.0f;
#pragma unroll
    for (int i = 0; i < 12; i++) {
        v[i] = __expf(v[i] - mx);
        sum += v[i];
    }
    red[tid] = sum;
    __syncthreads();
    for (int s = 128; s > 0; s >>= 1) {
        if (tid < s) red[tid] += red[tid + s];
        __syncthreads();
    }
    const float inv = 1.0f / red[0];
#pragma unroll
    for (int i = 0; i < 12; i++) p[tid + i * 256] = v[i] * inv;
}

// ---------------- h = LayerNorm(h + x) * g + b (block per row, D=1024) ---------
__global__ void __launch_bounds__(256)
add_ln_kernel(float* __restrict__ h, const float* __restrict__ x,
              const float* __restrict__ g, const float* __restrict__ b)
{
    const long row = blockIdx.x;
    float* hp = h + row * (long)DIM;
    const float* xp = x + row * (long)DIM;
    const int tid = threadIdx.x;

    float v[4];
    float sum = 0.0f;
#pragma unroll
    for (int i = 0; i < 4; i++) {
        const int c = tid + i * 256;
        v[i] = hp[c] + xp[c];
        sum += v[i];
    }
    __shared__ float red[256];
    red[tid] = sum;
    __syncthreads();
    for (int s = 128; s > 0; s >>= 1) {
        if (tid < s) red[tid] += red[tid + s];
        __syncthreads();
    }
    const float mu = red[0] * (1.0f / DIM);
    __syncthreads();

    float vs = 0.0f;
#pragma unroll
    for (int i = 0; i < 4; i++) {
        const float d = v[i] - mu;
        vs += d * d;
    }
    red[tid] = vs;
    __syncthreads();
    for (int s = 128; s > 0; s >>= 1) {
        if (tid < s) red[tid] += red[tid + s];
        __syncthreads();
    }
    const float inv = rsqrtf(red[0] * (1.0f / DIM) + LN_EPS);
    __syncthreads();
#pragma unroll
    for (int i = 0; i < 4; i++) {
        const int c = tid + i * 256;
        hp[c] = g[c] * (v[i] - mu) * inv + b[c];
    }
}

// ---------------- output heads: warp-per-output dot products -------------------
__global__ void __launch_bounds__(256)
heads_kernel(const float* __restrict__ h, const float* __restrict__ Whead,
             const float* __restrict__ bhead, const int* __restrict__ nev,
             const int* __restrict__ nag, float* __restrict__ out, int total)
{
    const int warpId = (blockIdx.x * blockDim.x + threadIdx.x) >> 5;
    const int lane = threadIdx.x & 31;
    if (warpId >= total) return;
    const int NEv = *nev;
    const int NAg = *nag;
    int headIdx, token;
    if (warpId < 3 * NAg) {
        headIdx = warpId / NAg;
        token = NEv + warpId % NAg;
    } else {
        headIdx = 3;
        token = warpId - 3 * NAg;
    }
    const float* hr = h + (long)token * DIM;
    const float* w = Whead + (long)headIdx * DIM;
    float s = 0.0f;
    for (int i = lane; i < DIM; i += 32) s = fmaf(hr[i], w[i], s);
#pragma unroll
    for (int off = 16; off > 0; off >>= 1) s += __shfl_down_sync(0xFFFFFFFFu, s, off);
    if (lane == 0) out[warpId] = s + bhead[headIdx];
}

__global__ void copy_kernel(float4* __restrict__ dst, const float4* __restrict__ src, int n4)
{
    const int i = blockIdx.x * blockDim.x + threadIdx.x;
    if (i < n4) dst[i] = src[i];
}

// ---------------- host orchestration -------------------------------------------
static void launch_gemm(const float* A, const float* B, const float* bias, float* C,
                        int M, int N, int K, int lda, int ldb, int ldc,
                        long sA, long sB, long sBias, long sC,
                        int batch, float alpha, int relu, bool transB)
{
    dim3 grid(N / 128, M / 128, batch);
    if (transB)
        gemm_kernel<true><<<grid, 256>>>(A, B, bias, C, M, N, K, lda, ldb, ldc,
                                         sA, sB, sBias, sC, alpha, relu);
    else
        gemm_kernel<false><<<grid, 256>>>(A, B, bias, C, M, N, K, lda, ldb, ldc,
                                          sA, sB, sBias, sC, alpha, relu);
}

extern "C" void kernel_launch(void* const* d_in, const int* in_sizes, int n_in,
                              void* d_out, int out_size)
{
    const float* hidden = (const float*)d_in[0];
    const float* Wq = (const float*)d_in[1];
    const float* bq = (const float*)d_in[2];
    const float* Wk = (const float*)d_in[3];
    const float* bk = (const float*)d_in[4];
    const float* Wv = (const float*)d_in[5];
    const float* bv = (const float*)d_in[6];
    const float* Wh = (const float*)d_in[7];
    const float* bh = (const float*)d_in[8];
    const float* Wo = (const float*)d_in[9];
    const float* bo = (const float*)d_in[10];
    const float* g1 = (const float*)d_in[11];
    const float* b1n = (const float*)d_in[12];
    const float* g2 = (const float*)d_in[13];
    const float* b2n = (const float*)d_in[14];
    const float* Wf1 = (const float*)d_in[15];
    const float* bf1 = (const float*)d_in[16];
    const float* Wf2 = (const float*)d_in[17];
    const float* bf2 = (const float*)d_in[18];
    const float* Whead = (const float*)d_in[19];
    const float* bhead = (const float*)d_in[20];
    const int* n_events = (const int*)d_in[21];
    const int* n_agents = (const int*)d_in[22];
    (void)in_sizes; (void)n_in;

    float *h, *Qb, *Kb, *Vb, *Qh, *Kh, *Vh, *scores, *ctx, *tmp, *ffn1;
    cudaGetSymbolAddress((void**)&h, g_h);
    cudaGetSymbolAddress((void**)&Qb, g_Q);
    cudaGetSymbolAddress((void**)&Kb, g_K);
    cudaGetSymbolAddress((void**)&Vb, g_V);
    cudaGetSymbolAddress((void**)&Qh, g_Qh);
    cudaGetSymbolAddress((void**)&Kh, g_Kh);
    cudaGetSymbolAddress((void**)&Vh, g_Vh);
    cudaGetSymbolAddress((void**)&scores, g_scores);
    cudaGetSymbolAddress((void**)&ctx, g_ctx);
    cudaGetSymbolAddress((void**)&tmp, g_tmp);
    cudaGetSymbolAddress((void**)&ffn1, g_ffn1);

    const int n4 = SEQ * DIM / 4;
    copy_kernel<<<(n4 + 255) / 256, 256>>>((float4*)h, (const float4*)hidden, n4);

    const long DD = (long)DIM * DIM;
    const long WhL = (long)NHEAD * DIM * DHEAD;
    const float attn_scale = 1.0f / 16.0f;  // 1/sqrt(256)

    for (int l = 0; l < NLAYER; l++) {
        // Q, K, V projections
        launch_gemm(h, Wq + l * DD, bq + (long)l * DIM, Qb, SEQ, DIM, DIM, DIM, DIM, DIM,
                    0, 0, 0, 0, 1, 1.0f, 0, false);
        launch_gemm(h, Wk + l * DD, bk + (long)l * DIM, Kb, SEQ, DIM, DIM, DIM, DIM, DIM,
                    0, 0, 0, 0, 1, 1.0f, 0, false);
        launch_gemm(h, Wv + l * DD, bv + (long)l * DIM, Vb, SEQ, DIM, DIM, DIM, DIM, DIM,
                    0, 0, 0, 0, 1, 1.0f, 0, false);
        // per-head projections (batched over heads)
        launch_gemm(Qb, Wh + l * WhL, bh + (long)l * NHEAD * DHEAD, Qh,
                    SEQ, DHEAD, DIM, DIM, DHEAD, DHEAD,
                    0, (long)DIM * DHEAD, DHEAD, (long)SEQ * DHEAD, NHEAD, 1.0f, 0, false);
        launch_gemm(Kb, Wh + l * WhL, bh + (long)l * NHEAD * DHEAD, Kh,
                    SEQ, DHEAD, DIM, DIM, DHEAD, DHEAD,
                    0, (long)DIM * DHEAD, DHEAD, (long)SEQ * DHEAD, NHEAD, 1.0f, 0, false);
        launch_gemm(Vb, Wh + l * WhL, bh + (long)l * NHEAD * DHEAD, Vh,
                    SEQ, DHEAD, DIM, DIM, DHEAD, DHEAD,
                    0, (long)DIM * DHEAD, DHEAD, (long)SEQ * DHEAD, NHEAD, 1.0f, 0, false);
        // scores = scale * Qh @ Kh^T  (batched over heads)
        launch_gemm(Qh, Kh, nullptr, scores, SEQ, SEQ, DHEAD, DHEAD, DHEAD, SEQ,
                    (long)SEQ * DHEAD, (long)SEQ * DHEAD, 0, (long)SEQ * SEQ,
                    NHEAD, attn_scale, 0, true);
        // softmax rows
        softmax_kernel<<<NHEAD * SEQ, 256>>>(scores);
        // ctx = attn @ Vh, written directly into (s, head*DHEAD+e) layout
        launch_gemm(scores, Vh, nullptr, ctx, SEQ, DHEAD, SEQ, SEQ, DHEAD, DIM,
                    (long)SEQ * SEQ, (long)SEQ * DHEAD, 0, (long)DHEAD,
                    NHEAD, 1.0f, 0, false);
        // attn_out = ctx @ Wo + bo
        launch_gemm(ctx, Wo + l * DD, bo + (long)l * DIM, tmp, SEQ, DIM, DIM, DIM, DIM, DIM,
                    0, 0, 0, 0, 1, 1.0f, 0, false);
        add_ln_kernel<<<SEQ, 256>>>(h, tmp, g1 + (long)l * DIM, b1n + (long)l * DIM);
        // FFN
        launch_gemm(h, Wf1 + (long)l * DIM * 2 * DIM, bf1 + (long)l * 2 * DIM, ffn1,
                    SEQ, 2 * DIM, DIM, DIM, 2 * DIM, 2 * DIM,
                    0, 0, 0, 0, 1, 1.0f, 1, false);
        launch_gemm(ffn1, Wf2 + (long)l * 2 * DIM * DIM, bf2 + (long)l * DIM, tmp,
                    SEQ, DIM, 2 * DIM, 2 * DIM, DIM, DIM,
                    0, 0, 0, 0, 1, 1.0f, 0, false);
        add_ln_kernel<<<SEQ, 256>>>(h, tmp, g2 + (long)l * DIM, b2n + (long)l * DIM);
    }

    // output heads
    const int blocks = (out_size * 32 + 255) / 256;
    heads_kernel<<<blocks, 256>>>(h, Whead, bhead, n_events, n_agents,
                                  (float*)d_out, out_size);
}

// round 2
// speedup vs baseline: 1.2255x; 1.2255x over previous
#include <cuda_runtime.h>
#include <math.h>

#define SEQ 3072
#define DIM 1024
#define NHEAD 4
#define DHEAD 256
#define NLAYER 4
#define LN_EPS 1e-5f

// ---------------- scratch (static device arrays; no allocation) ----------------
__device__ float g_h[SEQ * DIM];
__device__ float g_Q[SEQ * DIM];
__device__ float g_K[SEQ * DIM];
__device__ float g_V[SEQ * DIM];
__device__ float g_Qh[SEQ * DIM];   // [head][s][e]
__device__ float g_Kh[SEQ * DIM];
__device__ float g_Vh[SEQ * DIM];
__device__ float g_scores[(size_t)NHEAD * SEQ * SEQ];
__device__ float g_ctx[SEQ * DIM];  // [s][head*DHEAD+e]
__device__ float g_tmp[SEQ * DIM];
__device__ float g_ffn1[SEQ * 2 * DIM];

// ---------------- tiled SGEMM: C = alpha*A@op(B) + bias (opt relu) -------------
// 128x128 tile, BK=16, double-buffered smem, register-staged global loads.
// A: M x K row-major (lda). B normal: K x N row-major (ldb). B trans: N x K (ldb).
// Batched over blockIdx.z. Requires M%128==0, N%128==0, K%16==0.
#define SPITCH 132   // 132 floats = 528 B, 16B-aligned rows, 2-way store conflicts

template <bool TRANSB>
__global__ void __launch_bounds__(256, 2)
gemm_kernel(const float* __restrict__ Ag, const float* __restrict__ Bg,
            const float* __restrict__ biasg, float* __restrict__ Cg,
            int M, int N, int K, int lda, int ldb, int ldc,
            long sA, long sB, long sBias, long sC,
            float alpha, int relu)
{
    const float* Ap = Ag + sA * blockIdx.z;
    const float* Bp = Bg + sB * blockIdx.z;
    const float* biasp = biasg ? (biasg + sBias * blockIdx.z) : nullptr;
    float* Cp = Cg + sC * blockIdx.z;

    __shared__ float As[2][16][SPITCH];
    __shared__ float Bs[2][16][SPITCH];

    const int tid = threadIdx.x;
    const int tx = tid & 15;        // 0..15 -> N
    const int ty = tid >> 4;        // 0..15 -> M
    const int row0 = blockIdx.y * 128;
    const int col0 = blockIdx.x * 128;

    // loader indices: 128 rows x 16 k per tile, 2 float4 per thread
    const int lr = tid >> 2;          // 0..63
    const int lk = (tid & 3) * 4;     // 0,4,8,12
    // B-normal loader: 16 k-rows x 128 n
    const int bkr = tid >> 5;         // 0..7
    const int bc = (tid & 31) * 4;    // 0..124

    // ---- prologue: tile 0 straight into smem buffer 0 ----
    {
        float4 v0 = *(const float4*)(Ap + (long)(row0 + lr) * lda + lk);
        float4 v1 = *(const float4*)(Ap + (long)(row0 + lr + 64) * lda + lk);
        As[0][lk + 0][lr] = v0.x; As[0][lk + 1][lr] = v0.y;
        As[0][lk + 2][lr] = v0.z; As[0][lk + 3][lr] = v0.w;
        As[0][lk + 0][lr + 64] = v1.x; As[0][lk + 1][lr + 64] = v1.y;
        As[0][lk + 2][lr + 64] = v1.z; As[0][lk + 3][lr + 64] = v1.w;
        if (TRANSB) {
            float4 w0 = *(const float4*)(Bp + (long)(col0 + lr) * ldb + lk);
            float4 w1 = *(const float4*)(Bp + (long)(col0 + lr + 64) * ldb + lk);
            Bs[0][lk + 0][lr] = w0.x; Bs[0][lk + 1][lr] = w0.y;
            Bs[0][lk + 2][lr] = w0.z; Bs[0][lk + 3][lr] = w0.w;
            Bs[0][lk + 0][lr + 64] = w1.x; Bs[0][lk + 1][lr + 64] = w1.y;
            Bs[0][lk + 2][lr + 64] = w1.z; Bs[0][lk + 3][lr + 64] = w1.w;
        } else {
            float4 w0 = *(const float4*)(Bp + (long)bkr * ldb + col0 + bc);
            float4 w1 = *(const float4*)(Bp + (long)(bkr + 8) * ldb + col0 + bc);
            *(float4*)&Bs[0][bkr][bc] = w0;
            *(float4*)&Bs[0][bkr + 8][bc] = w1;
        }
    }
    __syncthreads();

    float acc[8][8];
#pragma unroll
    for (int i = 0; i < 8; i++)
#pragma unroll
        for (int j = 0; j < 8; j++) acc[i][j] = 0.0f;

    int buf = 0;
    for (int k0 = 0; k0 < K; k0 += 16) {
        const bool more = (k0 + 16) < K;
        float4 a0, a1, b0, b1;
        if (more) {
            const int kn = k0 + 16;
            a0 = *(const float4*)(Ap + (long)(row0 + lr) * lda + kn + lk);
            a1 = *(const float4*)(Ap + (long)(row0 + lr + 64) * lda + kn + lk);
            if (TRANSB) {
                b0 = *(const float4*)(Bp + (long)(col0 + lr) * ldb + kn + lk);
                b1 = *(const float4*)(Bp + (long)(col0 + lr + 64) * ldb + kn + lk);
            } else {
                b0 = *(const float4*)(Bp + (long)(kn + bkr) * ldb + col0 + bc);
                b1 = *(const float4*)(Bp + (long)(kn + bkr + 8) * ldb + col0 + bc);
            }
        }

#pragma unroll
        for (int kk = 0; kk < 16; kk++) {
            float4 aA = *(const float4*)&As[buf][kk][ty * 8];
            float4 aB = *(const float4*)&As[buf][kk][ty * 8 + 4];
            float4 bA = *(const float4*)&Bs[buf][kk][tx * 8];
            float4 bB = *(const float4*)&Bs[buf][kk][tx * 8 + 4];
            float a[8] = {aA.x, aA.y, aA.z, aA.w, aB.x, aB.y, aB.z, aB.w};
            float b[8] = {bA.x, bA.y, bA.z, bA.w, bB.x, bB.y, bB.z, bB.w};
#pragma unroll
            for (int i = 0; i < 8; i++)
#pragma unroll
                for (int j = 0; j < 8; j++) acc[i][j] = fmaf(a[i], b[j], acc[i][j]);
        }

        if (more) {
            const int nb = buf ^ 1;
            As[nb][lk + 0][lr] = a0.x; As[nb][lk + 1][lr] = a0.y;
            As[nb][lk + 2][lr] = a0.z; As[nb][lk + 3][lr] = a0.w;
            As[nb][lk + 0][lr + 64] = a1.x; As[nb][lk + 1][lr + 64] = a1.y;
            As[nb][lk + 2][lr + 64] = a1.z; As[nb][lk + 3][lr + 64] = a1.w;
            if (TRANSB) {
                Bs[nb][lk + 0][lr] = b0.x; Bs[nb][lk + 1][lr] = b0.y;
                Bs[nb][lk + 2][lr] = b0.z; Bs[nb][lk + 3][lr] = b0.w;
                Bs[nb][lk + 0][lr + 64] = b1.x; Bs[nb][lk + 1][lr + 64] = b1.y;
                Bs[nb][lk + 2][lr + 64] = b1.z; Bs[nb][lk + 3][lr + 64] = b1.w;
            } else {
                *(float4*)&Bs[nb][bkr][bc] = b0;
                *(float4*)&Bs[nb][bkr + 8][bc] = b1;
            }
            __syncthreads();
        }
        buf ^= 1;
    }

#pragma unroll
    for (int i = 0; i < 8; i++) {
        const long r = row0 + ty * 8 + i;
#pragma unroll
        for (int j = 0; j < 8; j += 4) {
            const int c = col0 + tx * 8 + j;
            float4 v;
            v.x = acc[i][j + 0] * alpha;
            v.y = acc[i][j + 1] * alpha;
            v.z = acc[i][j + 2] * alpha;
            v.w = acc[i][j + 3] * alpha;
            if (biasp) {
                v.x += biasp[c + 0];
                v.y += biasp[c + 1];
                v.z += biasp[c + 2];
                v.w += biasp[c + 3];
            }
            if (relu) {
                v.x = fmaxf(v.x, 0.0f);
                v.y = fmaxf(v.y, 0.0f);
                v.z = fmaxf(v.z, 0.0f);
                v.w = fmaxf(v.w, 0.0f);
            }
            *(float4*)(Cp + r * ldc + c) = v;
        }
    }
}

// ---------------- softmax over rows of length SEQ (block per row) --------------
__global__ void __launch_bounds__(256)
softmax_kernel(float* __restrict__ scores)
{
    const long row = blockIdx.x;
    float* p = scores + row * (long)SEQ;
    const int tid = threadIdx.x;

    float v[12];
    float mx = -1e30f;
#pragma unroll
    for (int i = 0; i < 12; i++) {
        v[i] = p[tid + i * 256];
        mx = fmaxf(mx, v[i]);
    }
    __shared__ float red[256];
    red[tid] = mx;
    __syncthreads();
    for (int s = 128; s > 0; s >>= 1) {
        if (tid < s) red[tid] = fmaxf(red[tid], red[tid + s]);
        __syncthreads();
    }
    mx = red[0];
    __syncthreads();

    float sum = 0.0f;
#pragma unroll
    for (int i = 0; i < 12; i++) {
        v[i] = __expf(v[i] - mx);
        sum += v[i];
    }
    red[tid] = sum;
    __syncthreads();
    for (int s = 128; s > 0; s >>= 1) {
        if (tid < s) red[tid] += red[tid + s];
        __syncthreads();
    }
    const float inv = 1.0f / red[0];
#pragma unroll
    for (int i = 0; i < 12; i++) p[tid + i * 256] = v[i] * inv;
}

// ---------------- h = LayerNorm(h + x) * g + b (block per row, D=1024) ---------
__global__ void __launch_bounds__(256)
add_ln_kernel(float* __restrict__ h, const float* __restrict__ x,
              const float* __restrict__ g, const float* __restrict__ b)
{
    const long row = blockIdx.x;
    float* hp = h + row * (long)DIM;
    const float* xp = x + row * (long)DIM;
    const int tid = threadIdx.x;

    float v[4];
    float sum = 0.0f;
#pragma unroll
    for (int i = 0; i < 4; i++) {
        const int c = tid + i * 256;
        v[i] = hp[c] + xp[c];
        sum += v[i];
    }
    __shared__ float red[256];
    red[tid] = sum;
    __syncthreads();
    for (int s = 128; s > 0; s >>= 1) {
        if (tid < s) red[tid] += red[tid + s];
        __syncthreads();
    }
    const float mu = red[0] * (1.0f / DIM);
    __syncthreads();

    float vs = 0.0f;
#pragma unroll
    for (int i = 0; i < 4; i++) {
        const float d = v[i] - mu;
        vs += d * d;
    }
    red[tid] = vs;
    __syncthreads();
    for (int s = 128; s > 0; s >>= 1) {
        if (tid < s) red[tid] += red[tid + s];
        __syncthreads();
    }
    const float inv = rsqrtf(red[0] * (1.0f / DIM) + LN_EPS);
    __syncthreads();
#pragma unroll
    for (int i = 0; i < 4; i++) {
        const int c = tid + i * 256;
        hp[c] = g[c] * (v[i] - mu) * inv + b[c];
    }
}

// ---------------- output heads: warp-per-output dot products -------------------
__global__ void __launch_bounds__(256)
heads_kernel(const float* __restrict__ h, const float* __restrict__ Whead,
             const float* __restrict__ bhead, const int* __restrict__ nev,
             const int* __restrict__ nag, float* __restrict__ out, int total)
{
    const int warpId = (blockIdx.x * blockDim.x + threadIdx.x) >> 5;
    const int lane = threadIdx.x & 31;
    if (warpId >= total) return;
    const int NEv = *nev;
    const int NAg = *nag;
    int headIdx, token;
    if (warpId < 3 * NAg) {
        headIdx = warpId / NAg;
        token = NEv + warpId % NAg;
    } else {
        headIdx = 3;
        token = warpId - 3 * NAg;
    }
    const float* hr = h + (long)token * DIM;
    const float* w = Whead + (long)headIdx * DIM;
    float s = 0.0f;
    for (int i = lane; i < DIM; i += 32) s = fmaf(hr[i], w[i], s);
#pragma unroll
    for (int off = 16; off > 0; off >>= 1) s += __shfl_down_sync(0xFFFFFFFFu, s, off);
    if (lane == 0) out[warpId] = s + bhead[headIdx];
}

__global__ void copy_kernel(float4* __restrict__ dst, const float4* __restrict__ src, int n4)
{
    const int i = blockIdx.x * blockDim.x + threadIdx.x;
    if (i < n4) dst[i] = src[i];
}

// ---------------- host orchestration -------------------------------------------
static void launch_gemm(const float* A, const float* B, const float* bias, float* C,
                        int M, int N, int K, int lda, int ldb, int ldc,
                        long sA, long sB, long sBias, long sC,
                        int batch, float alpha, int relu, bool transB)
{
    dim3 grid(N / 128, M / 128, batch);
    if (transB)
        gemm_kernel<true><<<grid, 256>>>(A, B, bias, C, M, N, K, lda, ldb, ldc,
                                         sA, sB, sBias, sC, alpha, relu);
    else
        gemm_kernel<false><<<grid, 256>>>(A, B, bias, C, M, N, K, lda, ldb, ldc,
                                          sA, sB, sBias, sC, alpha, relu);
}

extern "C" void kernel_launch(void* const* d_in, const int* in_sizes, int n_in,
                              void* d_out, int out_size)
{
    const float* hidden = (const float*)d_in[0];
    const float* Wq = (const float*)d_in[1];
    const float* bq = (const float*)d_in[2];
    const float* Wk = (const float*)d_in[3];
    const float* bk = (const float*)d_in[4];
    const float* Wv = (const float*)d_in[5];
    const float* bv = (const float*)d_in[6];
    const float* Wh = (const float*)d_in[7];
    const float* bh = (const float*)d_in[8];
    const float* Wo = (const float*)d_in[9];
    const float* bo = (const float*)d_in[10];
    const float* g1 = (const float*)d_in[11];
    const float* b1n = (const float*)d_in[12];
    const float* g2 = (const float*)d_in[13];
    const float* b2n = (const float*)d_in[14];
    const float* Wf1 = (const float*)d_in[15];
    const float* bf1 = (const float*)d_in[16];
    const float* Wf2 = (const float*)d_in[17];
    const float* bf2 = (const float*)d_in[18];
    const float* Whead = (const float*)d_in[19];
    const float* bhead = (const float*)d_in[20];
    const int* n_events = (const int*)d_in[21];
    const int* n_agents = (const int*)d_in[22];
    (void)in_sizes; (void)n_in;

    float *h, *Qb, *Kb, *Vb, *Qh, *Kh, *Vh, *scores, *ctx, *tmp, *ffn1;
    cudaGetSymbolAddress((void**)&h, g_h);
    cudaGetSymbolAddress((void**)&Qb, g_Q);
    cudaGetSymbolAddress((void**)&Kb, g_K);
    cudaGetSymbolAddress((void**)&Vb, g_V);
    cudaGetSymbolAddress((void**)&Qh, g_Qh);
    cudaGetSymbolAddress((void**)&Kh, g_Kh);
    cudaGetSymbolAddress((void**)&Vh, g_Vh);
    cudaGetSymbolAddress((void**)&scores, g_scores);
    cudaGetSymbolAddress((void**)&ctx, g_ctx);
    cudaGetSymbolAddress((void**)&tmp, g_tmp);
    cudaGetSymbolAddress((void**)&ffn1, g_ffn1);

    const int n4 = SEQ * DIM / 4;
    copy_kernel<<<(n4 + 255) / 256, 256>>>((float4*)h, (const float4*)hidden, n4);

    const long DD = (long)DIM * DIM;
    const long WhL = (long)NHEAD * DIM * DHEAD;
    const float attn_scale = 1.0f / 16.0f;  // 1/sqrt(256)

    for (int l = 0; l < NLAYER; l++) {
        // Q, K, V projections
        launch_gemm(h, Wq + l * DD, bq + (long)l * DIM, Qb, SEQ, DIM, DIM, DIM, DIM, DIM,
                    0, 0, 0, 0, 1, 1.0f, 0, false);
        launch_gemm(h, Wk + l * DD, bk + (long)l * DIM, Kb, SEQ, DIM, DIM, DIM, DIM, DIM,
                    0, 0, 0, 0, 1, 1.0f, 0, false);
        launch_gemm(h, Wv + l * DD, bv + (long)l * DIM, Vb, SEQ, DIM, DIM, DIM, DIM, DIM,
                    0, 0, 0, 0, 1, 1.0f, 0, false);
        // per-head projections (batched over heads)
        launch_gemm(Qb, Wh + l * WhL, bh + (long)l * NHEAD * DHEAD, Qh,
                    SEQ, DHEAD, DIM, DIM, DHEAD, DHEAD,
                    0, (long)DIM * DHEAD, DHEAD, (long)SEQ * DHEAD, NHEAD, 1.0f, 0, false);
        launch_gemm(Kb, Wh + l * WhL, bh + (long)l * NHEAD * DHEAD, Kh,
                    SEQ, DHEAD, DIM, DIM, DHEAD, DHEAD,
                    0, (long)DIM * DHEAD, DHEAD, (long)SEQ * DHEAD, NHEAD, 1.0f, 0, false);
        launch_gemm(Vb, Wh + l * WhL, bh + (long)l * NHEAD * DHEAD, Vh,
                    SEQ, DHEAD, DIM, DIM, DHEAD, DHEAD,
                    0, (long)DIM * DHEAD, DHEAD, (long)SEQ * DHEAD, NHEAD, 1.0f, 0, false);
        // scores = scale * Qh @ Kh^T  (batched over heads)
        launch_gemm(Qh, Kh, nullptr, scores, SEQ, SEQ, DHEAD, DHEAD, DHEAD, SEQ,
                    (long)SEQ * DHEAD, (long)SEQ * DHEAD, 0, (long)SEQ * SEQ,
                    NHEAD, attn_scale, 0, true);
        // softmax rows
        softmax_kernel<<<NHEAD * SEQ, 256>>>(scores);
        // ctx = attn @ Vh, written directly into (s, head*DHEAD+e) layout
        launch_gemm(scores, Vh, nullptr, ctx, SEQ, DHEAD, SEQ, SEQ, DHEAD, DIM,
                    (long)SEQ * SEQ, (long)SEQ * DHEAD, 0, (long)DHEAD,
                    NHEAD, 1.0f, 0, false);
        // attn_out = ctx @ Wo + bo
        launch_gemm(ctx, Wo + l * DD, bo + (long)l * DIM, tmp, SEQ, DIM, DIM, DIM, DIM, DIM,
                    0, 0, 0, 0, 1, 1.0f, 0, false);
        add_ln_kernel<<<SEQ, 256>>>(h, tmp, g1 + (long)l * DIM, b1n + (long)l * DIM);
        // FFN
        launch_gemm(h, Wf1 + (long)l * DIM * 2 * DIM, bf1 + (long)l * 2 * DIM, ffn1,
                    SEQ, 2 * DIM, DIM, DIM, 2 * DIM, 2 * DIM,
                    0, 0, 0, 0, 1, 1.0f, 1, false);
        launch_gemm(ffn1, Wf2 + (long)l * 2 * DIM * DIM, bf2 + (long)l * DIM, tmp,
                    SEQ, DIM, 2 * DIM, 2 * DIM, DIM, DIM,
                    0, 0, 0, 0, 1, 1.0f, 0, false);
        add_ln_kernel<<<SEQ, 256>>>(h, tmp, g2 + (long)l * DIM, b2n + (long)l * DIM);
    }

    // output heads
    const int blocks = (out_size * 32 + 255) / 256;
    heads_kernel<<<blocks, 256>>>(h, Whead, bhead, n_events, n_agents,
                                  (float*)d_out, out_size);
}

// round 4
// speedup vs baseline: 3.2175x; 2.6253x over previous
#include <cuda_runtime.h>
#include <cuda_bf16.h>
#include <cstdint>
#include <math.h>

#define SEQ 3072
#define DIM 1024
#define NHEAD 4
#define DHEAD 256
#define NLAYER 4
#define LN_EPS 1e-5f
typedef __nv_bfloat16 bf16;

// ======================= scratch (static device arrays) =======================
__device__ float g_h[SEQ * DIM];
__device__ float g_tmp[SEQ * DIM];
__device__ float g_vh[SEQ * DIM];                      // [head][t][e] f32
__device__ float g_scores[(size_t)NHEAD * SEQ * SEQ];

__device__ bf16 g_h_hi[SEQ * DIM],   g_h_lo[SEQ * DIM];
__device__ bf16 g_q_hi[SEQ * DIM],   g_q_lo[SEQ * DIM];
__device__ bf16 g_k_hi[SEQ * DIM],   g_k_lo[SEQ * DIM];
__device__ bf16 g_v_hi[SEQ * DIM],   g_v_lo[SEQ * DIM];
__device__ bf16 g_qh_hi[SEQ * DIM],  g_qh_lo[SEQ * DIM];   // [head][t][e]
__device__ bf16 g_kh_hi[SEQ * DIM],  g_kh_lo[SEQ * DIM];
__device__ bf16 g_vht_hi[SEQ * DIM], g_vht_lo[SEQ * DIM];  // [head][e][t]
__device__ bf16 g_ctx_hi[SEQ * DIM], g_ctx_lo[SEQ * DIM];  // [t][head*DHEAD+e]
__device__ bf16 g_f1_hi[SEQ * 2 * DIM], g_f1_lo[SEQ * 2 * DIM];
__device__ bf16 g_at_hi[(size_t)NHEAD * SEQ * SEQ];
__device__ bf16 g_at_lo[(size_t)NHEAD * SEQ * SEQ];

// transposed weights [N][K] bf16 hi/lo
__device__ bf16 g_wqt_hi[NLAYER * DIM * DIM],  g_wqt_lo[NLAYER * DIM * DIM];
__device__ bf16 g_wkt_hi[NLAYER * DIM * DIM],  g_wkt_lo[NLAYER * DIM * DIM];
__device__ bf16 g_wvt_hi[NLAYER * DIM * DIM],  g_wvt_lo[NLAYER * DIM * DIM];
__device__ bf16 g_wot_hi[NLAYER * DIM * DIM],  g_wot_lo[NLAYER * DIM * DIM];
__device__ bf16 g_wht_hi[NLAYER * NHEAD * DIM * DHEAD], g_wht_lo[NLAYER * NHEAD * DIM * DHEAD];
__device__ bf16 g_w1t_hi[NLAYER * DIM * 2 * DIM], g_w1t_lo[NLAYER * DIM * 2 * DIM];
__device__ bf16 g_w2t_hi[NLAYER * 2 * DIM * DIM], g_w2t_lo[NLAYER * 2 * DIM * DIM];

// ======================= helpers =======================
__device__ __forceinline__ uint32_t s2u(const void* p) {
    uint32_t a;
    asm("{ .reg .u64 t; cvta.to.shared.u64 t, %1; cvt.u32.u64 %0, t; }" : "=r"(a) : "l"(p));
    return a;
}
__device__ __forceinline__ void split2(float x, bf16& h, bf16& l) {
    h = __float2bfloat16(x);
    l = __float2bfloat16(x - __bfloat162float(h));
}
__device__ __forceinline__ void cp16(uint32_t dst, const void* src) {
    asm volatile("cp.async.cg.shared.global [%0], [%1], 16;" :: "r"(dst), "l"(src) : "memory");
}
#define CP_COMMIT() asm volatile("cp.async.commit_group;" ::: "memory")
#define CP_WAIT(n)  asm volatile("cp.async.wait_group %0;" :: "n"(n) : "memory")

__device__ __forceinline__ void ldm_x4(uint32_t* r, uint32_t addr) {
    asm volatile("ldmatrix.sync.aligned.m8n8.x4.shared.b16 {%0,%1,%2,%3}, [%4];"
                 : "=r"(r[0]), "=r"(r[1]), "=r"(r[2]), "=r"(r[3]) : "r"(addr));
}
__device__ __forceinline__ void mma_bf16(float* c, const uint32_t* a, const uint32_t* b) {
    asm volatile(
        "mma.sync.aligned.m16n8k16.row.col.f32.bf16.bf16.f32 "
        "{%0,%1,%2,%3}, {%4,%5,%6,%7}, {%8,%9}, {%0,%1,%2,%3};"
        : "+f"(c[0]), "+f"(c[1]), "+f"(c[2]), "+f"(c[3])
        : "r"(a[0]), "r"(a[1]), "r"(a[2]), "r"(a[3]), "r"(b[0]), "r"(b[1]));
}

// ======================= split-bf16 mma.sync GEMM =======================
// C[m][n] = alpha * sum_k A[m][k]*B[n][k] + bias[n]   (A,B as hi/lo bf16)
// Tile 128x128, BK=64 bf16, 2-stage cp.async pipeline, batched over z.
// Per-stage smem: Ahi/Alo/Bhi/Blo each 128 rows x 128 B (SW128) = 64 KB.
#define GSMEM_BYTES 131072

__global__ void __launch_bounds__(256, 1)
mma_gemm(const bf16* __restrict__ Ahi, const bf16* __restrict__ Alo, int lda, long sA,
         const bf16* __restrict__ Bhi, const bf16* __restrict__ Blo, int ldb, long sB,
         const float* __restrict__ bias, long sBias,
         float* __restrict__ C, bf16* __restrict__ Chi, bf16* __restrict__ Clo,
         int ldc, long sC, int K, float alpha, int relu)
{
    extern __shared__ char sm[];
    const uint32_t sb = s2u(sm);
    const int tid = threadIdx.x;
    const int wid = tid >> 5;
    const int lane = tid & 31;
    const int wm = wid >> 2;        // 0..1  (M)
    const int wn = wid & 3;         // 0..3  (N)
    const int z = blockIdx.z;
    const long row0 = (long)blockIdx.y * 128;
    const long col0 = (long)blockIdx.x * 128;

    Ahi += sA * z; Alo += sA * z; Bhi += sB * z; Blo += sB * z;

    const int nch = K >> 6;

    // ---- async load of one 64-k chunk into stage buffer ----
    auto load_chunk = [&](int ch, int buf) {
        const long k0 = (long)ch << 6;
#pragma unroll
        for (int i = 0; i < 16; i++) {
            const int u = tid + (i << 8);
            const int t = u >> 10;          // 0=Ahi 1=Alo 2=Bhi 3=Blo
            const int q = u & 1023;         // row*8 + seg
            const long r = q >> 3;
            const int sg = (q & 7) << 3;    // bf16 offset within chunk
            const bf16* p;
            if (t == 0)      p = Ahi + (row0 + r) * lda;
            else if (t == 1) p = Alo + (row0 + r) * lda;
            else if (t == 2) p = Bhi + (col0 + r) * ldb;
            else             p = Blo + (col0 + r) * ldb;
            uint32_t off = (uint32_t)(q << 4);            // row*128 + seg*16
            off ^= (off >> 3) & 0x70;                      // SW128
            cp16(sb + (uint32_t)buf * 65536u + (uint32_t)t * 16384u + off, p + k0 + sg);
        }
        CP_COMMIT();
    };

    float acc[4][4][4];
#pragma unroll
    for (int a = 0; a < 4; a++)
#pragma unroll
        for (int b = 0; b < 4; b++)
#pragma unroll
            for (int c = 0; c < 4; c++) acc[a][b][c] = 0.0f;

    load_chunk(0, 0);

    for (int ch = 0; ch < nch; ch++) {
        if (ch + 1 < nch) {
            load_chunk(ch + 1, (ch + 1) & 1);
            CP_WAIT(1);
        } else {
            CP_WAIT(0);
        }
        __syncthreads();

        const uint32_t stg = sb + (uint32_t)(ch & 1) * 65536u;

#pragma unroll
        for (int ks = 0; ks < 4; ks++) {
            uint32_t ah[4][4], al[4][4], bh[2][4], bl[2][4];
#pragma unroll
            for (int mt = 0; mt < 4; mt++) {
                const int row = wm * 64 + mt * 16 + (lane & 15);
                const int colb = ks * 32 + ((lane >> 4) << 4);
                uint32_t off = (uint32_t)(row * 128 + colb);
                off ^= (off >> 3) & 0x70;
                ldm_x4(ah[mt], stg + off);
                ldm_x4(al[mt], stg + 16384u + off);
            }
#pragma unroll
            for (int np = 0; np < 2; np++) {
                const int row = wn * 32 + np * 16 + (lane & 7) + ((lane >> 4) << 3);
                const int colb = ks * 32 + (((lane >> 3) & 1) << 4);
                uint32_t off = (uint32_t)(row * 128 + colb);
                off ^= (off >> 3) & 0x70;
                ldm_x4(bh[np], stg + 32768u + off);
                ldm_x4(bl[np], stg + 49152u + off);
            }
#pragma unroll
            for (int mt = 0; mt < 4; mt++)
#pragma unroll
                for (int nt = 0; nt < 4; nt++) {
                    const uint32_t* bhp = &bh[nt >> 1][(nt & 1) * 2];
                    const uint32_t* blp = &bl[nt >> 1][(nt & 1) * 2];
                    mma_bf16(acc[mt][nt], ah[mt], bhp);
                    mma_bf16(acc[mt][nt], ah[mt], blp);
                    mma_bf16(acc[mt][nt], al[mt], bhp);
                }
        }
        __syncthreads();
    }

    // -------- epilogue --------
    float* Cz = C ? C + sC * z : nullptr;
    bf16* Hz = Chi ? Chi + sC * z : nullptr;
    bf16* Lz = Clo ? Clo + sC * z : nullptr;
    const float* bz = bias ? bias + sBias * z : nullptr;

#pragma unroll
    for (int mt = 0; mt < 4; mt++)
#pragma unroll
        for (int nt = 0; nt < 4; nt++) {
            float* d = acc[mt][nt];
            const long gm = row0 + wm * 64 + mt * 16 + (lane >> 2);
            const long gn = col0 + wn * 32 + nt * 8 + (lane & 3) * 2;
            float b0 = 0.0f, b1 = 0.0f;
            if (bz) { b0 = __ldg(bz + gn); b1 = __ldg(bz + gn + 1); }
#pragma unroll
            for (int half = 0; half < 2; half++) {
                const long r = gm + half * 8;
                float x0 = d[half * 2 + 0] * alpha + b0;
                float x1 = d[half * 2 + 1] * alpha + b1;
                if (relu) { x0 = fmaxf(x0, 0.0f); x1 = fmaxf(x1, 0.0f); }
                const long o = r * ldc + gn;
                if (Cz) *(float2*)(Cz + o) = make_float2(x0, x1);
                if (Hz) {
                    bf16 h0, l0, h1, l1;
                    split2(x0, h0, l0); split2(x1, h1, l1);
                    uint32_t wh = (uint32_t)__bfloat16_as_ushort(h0) |
                                  ((uint32_t)__bfloat16_as_ushort(h1) << 16);
                    uint32_t wl = (uint32_t)__bfloat16_as_ushort(l0) |
                                  ((uint32_t)__bfloat16_as_ushort(l1) << 16);
                    *(uint32_t*)(Hz + o) = wh;
                    *(uint32_t*)(Lz + o) = wl;
                }
            }
        }
}

// ======================= transpose + split: [R][C] f32 -> [C][R] bf16 hi/lo ====
__global__ void __launch_bounds__(256)
transpose_split(const float* __restrict__ in, bf16* __restrict__ ohi, bf16* __restrict__ olo,
                int R, int Ccols, long sIn, long sOut)
{
    __shared__ float t[32][33];
    const float* ip = in + sIn * blockIdx.z;
    const int c0 = blockIdx.x * 32, r0 = blockIdx.y * 32;
    const int tx = threadIdx.x & 31, ty = threadIdx.x >> 5;
#pragma unroll
    for (int j = 0; j < 32; j += 8)
        t[ty + j][tx] = ip[(long)(r0 + ty + j) * Ccols + c0 + tx];
    __syncthreads();
#pragma unroll
    for (int j = 0; j < 32; j += 8) {
        float x = t[tx][ty + j];
        bf16 h, l; split2(x, h, l);
        long o = sOut * blockIdx.z + (long)(c0 + ty + j) * R + r0 + tx;
        ohi[o] = h; olo[o] = l;
    }
}

// ======================= copy + split =======================
__global__ void __launch_bounds__(256)
copy_split(const float* __restrict__ src, float* __restrict__ dst,
           bf16* __restrict__ dhi, bf16* __restrict__ dlo, int n)
{
    const int i = blockIdx.x * blockDim.x + threadIdx.x;
    if (i < n) {
        float v = src[i];
        dst[i] = v;
        bf16 h, l; split2(v, h, l);
        dhi[i] = h; dlo[i] = l;
    }
}

// ======================= softmax (f32 in, bf16 hi/lo out) =======================
__global__ void __launch_bounds__(256)
softmax_kernel(const float* __restrict__ scores, bf16* __restrict__ ohi, bf16* __restrict__ olo)
{
    const size_t base = (size_t)blockIdx.x * SEQ;
    const float* p = scores + base;
    const int tid = threadIdx.x;

    float v[12];
    float mx = -1e30f;
#pragma unroll
    for (int i = 0; i < 12; i++) {
        v[i] = p[tid + i * 256];
        mx = fmaxf(mx, v[i]);
    }
    __shared__ float red[256];
    red[tid] = mx;
    __syncthreads();
    for (int s = 128; s > 0; s >>= 1) {
        if (tid < s) red[tid] = fmaxf(red[tid], red[tid + s]);
        __syncthreads();
    }
    mx = red[0];
    __syncthreads();

    float sum = 0.0f;
#pragma unroll
    for (int i = 0; i < 12; i++) {
        v[i] = __expf(v[i] - mx);
        sum += v[i];
    }
    red[tid] = sum;
    __syncthreads();
    for (int s = 128; s > 0; s >>= 1) {
        if (tid < s) red[tid] += red[tid + s];
        __syncthreads();
    }
    const float inv = 1.0f / red[0];
#pragma unroll
    for (int i = 0; i < 12; i++) {
        float x = v[i] * inv;
        bf16 h, l; split2(x, h, l);
        ohi[base + tid + i * 256] = h;
        olo[base + tid + i * 256] = l;
    }
}

// ======================= add + layernorm (emit f32 + hi/lo) ====================
__global__ void __launch_bounds__(256)
add_ln_kernel(float* __restrict__ h, const float* __restrict__ x,
              const float* __restrict__ g, const float* __restrict__ b,
              bf16* __restrict__ ohi, bf16* __restrict__ olo)
{
    const long row = blockIdx.x;
    float* hp = h + row * (long)DIM;
    const float* xp = x + row * (long)DIM;
    const int tid = threadIdx.x;

    float v[4];
    float sum = 0.0f;
#pragma unroll
    for (int i = 0; i < 4; i++) {
        const int c = tid + i * 256;
        v[i] = hp[c] + xp[c];
        sum += v[i];
    }
    __shared__ float red[256];
    red[tid] = sum;
    __syncthreads();
    for (int s = 128; s > 0; s >>= 1) {
        if (tid < s) red[tid] += red[tid + s];
        __syncthreads();
    }
    const float mu = red[0] * (1.0f / DIM);
    __syncthreads();

    float vs = 0.0f;
#pragma unroll
    for (int i = 0; i < 4; i++) {
        const float d = v[i] - mu;
        vs += d * d;
    }
    red[tid] = vs;
    __syncthreads();
    for (int s = 128; s > 0; s >>= 1) {
        if (tid < s) red[tid] += red[tid + s];
        __syncthreads();
    }
    const float inv = rsqrtf(red[0] * (1.0f / DIM) + LN_EPS);
    __syncthreads();
#pragma unroll
    for (int i = 0; i < 4; i++) {
        const int c = tid + i * 256;
        float y = g[c] * (v[i] - mu) * inv + b[c];
        hp[c] = y;
        bf16 hh, ll; split2(y, hh, ll);
        ohi[row * (long)DIM + c] = hh;
        olo[row * (long)DIM + c] = ll;
    }
}

// ======================= output heads =======================
__global__ void __launch_bounds__(256)
heads_kernel(const float* __restrict__ h, const float* __restrict__ Whead,
             const float* __restrict__ bhead, const int* __restrict__ nev,
             const int* __restrict__ nag, float* __restrict__ out, int total)
{
    const int warpId = (blockIdx.x * blockDim.x + threadIdx.x) >> 5;
    const int lane = threadIdx.x & 31;
    if (warpId >= total) return;
    const int NEv = *nev;
    const int NAg = *nag;
    int headIdx, token;
    if (warpId < 3 * NAg) {
        headIdx = warpId / NAg;
        token = NEv + warpId % NAg;
    } else {
        headIdx = 3;
        token = warpId - 3 * NAg;
    }
    const float* hr = h + (long)token * DIM;
    const float* w = Whead + (long)headIdx * DIM;
    float s = 0.0f;
    for (int i = lane; i < DIM; i += 32) s = fmaf(hr[i], w[i], s);
#pragma unroll
    for (int off = 16; off > 0; off >>= 1) s += __shfl_down_sync(0xFFFFFFFFu, s, off);
    if (lane == 0) out[warpId] = s + bhead[headIdx];
}

// ======================= host orchestration =======================
static void tcg(const bf16* Ahi, const bf16* Alo, int lda, long sA,
                const bf16* Bhi, const bf16* Blo, int ldb, long sB,
                const float* bias, long sBias,
                float* C, bf16* Chi, bf16* Clo, int ldc, long sC,
                int M, int N, int K, int batch, float alpha, int relu)
{
    dim3 grid(N / 128, M / 128, batch);
    mma_gemm<<<grid, 256, GSMEM_BYTES>>>(Ahi, Alo, lda, sA, Bhi, Blo, ldb, sB,
                                         bias, sBias, C, Chi, Clo, ldc, sC, K, alpha, relu);
}

#define SYM(var, name) cudaGetSymbolAddress((void**)&var, name)

extern "C" void kernel_launch(void* const* d_in, const int* in_sizes, int n_in,
                              void* d_out, int out_size)
{
    const float* hidden = (const float*)d_in[0];
    const float* Wq = (const float*)d_in[1];
    const float* bq = (const float*)d_in[2];
    const float* Wk = (const float*)d_in[3];
    const float* bk = (const float*)d_in[4];
    const float* Wv = (const float*)d_in[5];
    const float* bv = (const float*)d_in[6];
    const float* Wh = (const float*)d_in[7];
    const float* bh = (const float*)d_in[8];
    const float* Wo = (const float*)d_in[9];
    const float* bo = (const float*)d_in[10];
    const float* g1 = (const float*)d_in[11];
    const float* b1n = (const float*)d_in[12];
    const float* g2 = (const float*)d_in[13];
    const float* b2n = (const float*)d_in[14];
    const float* Wf1 = (const float*)d_in[15];
    const float* bf1 = (const float*)d_in[16];
    const float* Wf2 = (const float*)d_in[17];
    const float* bf2 = (const float*)d_in[18];
    const float* Whead = (const float*)d_in[19];
    const float* bhead = (const float*)d_in[20];
    const int* n_events = (const int*)d_in[21];
    const int* n_agents = (const int*)d_in[22];
    (void)in_sizes; (void)n_in;

    cudaFuncSetAttribute(mma_gemm, cudaFuncAttributeMaxDynamicSharedMemorySize, GSMEM_BYTES);

    float *h, *tmp, *vh, *scores;
    SYM(h, g_h); SYM(tmp, g_tmp); SYM(vh, g_vh); SYM(scores, g_scores);
    bf16 *h_hi, *h_lo, *q_hi, *q_lo, *k_hi, *k_lo, *v_hi, *v_lo;
    bf16 *qh_hi, *qh_lo, *kh_hi, *kh_lo, *vht_hi, *vht_lo, *ctx_hi, *ctx_lo;
    bf16 *f1_hi, *f1_lo, *at_hi, *at_lo;
    SYM(h_hi, g_h_hi); SYM(h_lo, g_h_lo);
    SYM(q_hi, g_q_hi); SYM(q_lo, g_q_lo);
    SYM(k_hi, g_k_hi); SYM(k_lo, g_k_lo);
    SYM(v_hi, g_v_hi); SYM(v_lo, g_v_lo);
    SYM(qh_hi, g_qh_hi); SYM(qh_lo, g_qh_lo);
    SYM(kh_hi, g_kh_hi); SYM(kh_lo, g_kh_lo);
    SYM(vht_hi, g_vht_hi); SYM(vht_lo, g_vht_lo);
    SYM(ctx_hi, g_ctx_hi); SYM(ctx_lo, g_ctx_lo);
    SYM(f1_hi, g_f1_hi); SYM(f1_lo, g_f1_lo);
    SYM(at_hi, g_at_hi); SYM(at_lo, g_at_lo);
    bf16 *wqt_hi, *wqt_lo, *wkt_hi, *wkt_lo, *wvt_hi, *wvt_lo, *wot_hi, *wot_lo;
    bf16 *wht_hi, *wht_lo, *w1t_hi, *w1t_lo, *w2t_hi, *w2t_lo;
    SYM(wqt_hi, g_wqt_hi); SYM(wqt_lo, g_wqt_lo);
    SYM(wkt_hi, g_wkt_hi); SYM(wkt_lo, g_wkt_lo);
    SYM(wvt_hi, g_wvt_hi); SYM(wvt_lo, g_wvt_lo);
    SYM(wot_hi, g_wot_hi); SYM(wot_lo, g_wot_lo);
    SYM(wht_hi, g_wht_hi); SYM(wht_lo, g_wht_lo);
    SYM(w1t_hi, g_w1t_hi); SYM(w1t_lo, g_w1t_lo);
    SYM(w2t_hi, g_w2t_hi); SYM(w2t_lo, g_w2t_lo);

    const long DD = (long)DIM * DIM;
    const long SS = (long)SEQ * SEQ;
    const long SDh = (long)SEQ * DHEAD;

    // ---- weight transposes (per launch; deterministic) ----
    transpose_split<<<dim3(DIM / 32, DIM / 32, NLAYER), 256>>>(Wq, wqt_hi, wqt_lo, DIM, DIM, DD, DD);
    transpose_split<<<dim3(DIM / 32, DIM / 32, NLAYER), 256>>>(Wk, wkt_hi, wkt_lo, DIM, DIM, DD, DD);
    transpose_split<<<dim3(DIM / 32, DIM / 32, NLAYER), 256>>>(Wv, wvt_hi, wvt_lo, DIM, DIM, DD, DD);
    transpose_split<<<dim3(DIM / 32, DIM / 32, NLAYER), 256>>>(Wo, wot_hi, wot_lo, DIM, DIM, DD, DD);
    transpose_split<<<dim3(DHEAD / 32, DIM / 32, NLAYER * NHEAD), 256>>>(
        Wh, wht_hi, wht_lo, DIM, DHEAD, (long)DIM * DHEAD, (long)DIM * DHEAD);
    transpose_split<<<dim3(2 * DIM / 32, DIM / 32, NLAYER), 256>>>(Wf1, w1t_hi, w1t_lo, DIM, 2 * DIM, 2 * DD, 2 * DD);
    transpose_split<<<dim3(DIM / 32, 2 * DIM / 32, NLAYER), 256>>>(Wf2, w2t_hi, w2t_lo, 2 * DIM, DIM, 2 * DD, 2 * DD);

    const int n = SEQ * DIM;
    copy_split<<<(n + 255) / 256, 256>>>(hidden, h, h_hi, h_lo, n);

    const float attn_scale = 1.0f / 16.0f;

    for (int l = 0; l < NLAYER; l++) {
        const long WHL = (long)NHEAD * DIM * DHEAD;
        // Q, K, V projections -> hi/lo only
        tcg(h_hi, h_lo, DIM, 0, wqt_hi + l * DD, wqt_lo + l * DD, DIM, 0,
            bq + (long)l * DIM, 0, nullptr, q_hi, q_lo, DIM, 0, SEQ, DIM, DIM, 1, 1.0f, 0);
        tcg(h_hi, h_lo, DIM, 0, wkt_hi + l * DD, wkt_lo + l * DD, DIM, 0,
            bk + (long)l * DIM, 0, nullptr, k_hi, k_lo, DIM, 0, SEQ, DIM, DIM, 1, 1.0f, 0);
        tcg(h_hi, h_lo, DIM, 0, wvt_hi + l * DD, wvt_lo + l * DD, DIM, 0,
            bv + (long)l * DIM, 0, nullptr, v_hi, v_lo, DIM, 0, SEQ, DIM, DIM, 1, 1.0f, 0);
        // per-head projections (batch over heads)
        tcg(q_hi, q_lo, DIM, 0, wht_hi + l * WHL, wht_lo + l * WHL, DIM, (long)DIM * DHEAD,
            bh + (long)l * NHEAD * DHEAD, DHEAD, nullptr, qh_hi, qh_lo, DHEAD, SDh,
            SEQ, DHEAD, DIM, NHEAD, 1.0f, 0);
        tcg(k_hi, k_lo, DIM, 0, wht_hi + l * WHL, wht_lo + l * WHL, DIM, (long)DIM * DHEAD,
            bh + (long)l * NHEAD * DHEAD, DHEAD, nullptr, kh_hi, kh_lo, DHEAD, SDh,
            SEQ, DHEAD, DIM, NHEAD, 1.0f, 0);
        tcg(v_hi, v_lo, DIM, 0, wht_hi + l * WHL, wht_lo + l * WHL, DIM, (long)DIM * DHEAD,
            bh + (long)l * NHEAD * DHEAD, DHEAD, vh, nullptr, nullptr, DHEAD, SDh,
            SEQ, DHEAD, DIM, NHEAD, 1.0f, 0);
        // Vh [t][e] -> VhT [e][t] hi/lo
        transpose_split<<<dim3(DHEAD / 32, SEQ / 32, NHEAD), 256>>>(
            vh, vht_hi, vht_lo, SEQ, DHEAD, SDh, SDh);
        // scores = scale * Qh @ Kh^T
        tcg(qh_hi, qh_lo, DHEAD, SDh, kh_hi, kh_lo, DHEAD, SDh,
            nullptr, 0, scores, nullptr, nullptr, SEQ, SS,
            SEQ, SEQ, DHEAD, NHEAD, attn_scale, 0);
        // softmax -> attn hi/lo
        softmax_kernel<<<NHEAD * SEQ, 256>>>(scores, at_hi, at_lo);
        // ctx = attn @ Vh  -> hi/lo in [t][head*DHEAD+e] layout
        tcg(at_hi, at_lo, SEQ, SS, vht_hi, vht_lo, SEQ, (long)DHEAD * SEQ,
            nullptr, 0, nullptr, ctx_hi, ctx_lo, DIM, DHEAD,
            SEQ, DHEAD, SEQ, NHEAD, 1.0f, 0);
        // attn_out = ctx @ Wo + bo -> f32 tmp
        tcg(ctx_hi, ctx_lo, DIM, 0, wot_hi + l * DD, wot_lo + l * DD, DIM, 0,
            bo + (long)l * DIM, 0, tmp, nullptr, nullptr, DIM, 0, SEQ, DIM, DIM, 1, 1.0f, 0);
        add_ln_kernel<<<SEQ, 256>>>(h, tmp, g1 + (long)l * DIM, b1n + (long)l * DIM, h_hi, h_lo);
        // FFN
        tcg(h_hi, h_lo, DIM, 0, w1t_hi + l * 2 * DD, w1t_lo + l * 2 * DD, DIM, 0,
            bf1 + (long)l * 2 * DIM, 0, nullptr, f1_hi, f1_lo, 2 * DIM, 0,
            SEQ, 2 * DIM, DIM, 1, 1.0f, 1);
        tcg(f1_hi, f1_lo, 2 * DIM, 0, w2t_hi + l * 2 * DD, w2t_lo + l * 2 * DD, 2 * DIM, 0,
            bf2 + (long)l * DIM, 0, tmp, nullptr, nullptr, DIM, 0,
            SEQ, DIM, 2 * DIM, 1, 1.0f, 0);
        add_ln_kernel<<<SEQ, 256>>>(h, tmp, g2 + (long)l * DIM, b2n + (long)l * DIM, h_hi, h_lo);
    }

    const int blocks = (out_size * 32 + 255) / 256;
    heads_kernel<<<blocks, 256>>>(h, Whead, bhead, n_events, n_agents, (float*)d_out, out_size);
}

// round 5
// speedup vs baseline: 3.4720x; 1.0791x over previous
#include <cuda_runtime.h>
#include <cuda_bf16.h>
#include <cstdint>
#include <math.h>

#define SEQ 3072
#define DIM 1024
#define NHEAD 4
#define DHEAD 256
#define NLAYER 4
#define LN_EPS 1e-5f
typedef __nv_bfloat16 bf16;

// ======================= scratch (static device arrays) =======================
__device__ float g_h[SEQ * DIM];
__device__ float g_tmp[SEQ * DIM];
__device__ float g_scores[(size_t)NHEAD * SEQ * SEQ];

__device__ bf16 g_h_hi[SEQ * DIM],   g_h_lo[SEQ * DIM];
__device__ bf16 g_qkv_hi[3 * SEQ * DIM],  g_qkv_lo[3 * SEQ * DIM];   // [qkv][t][d]
__device__ bf16 g_qkvh_hi[3 * SEQ * DIM], g_qkvh_lo[3 * SEQ * DIM];  // [qkv][head][t][e]
__device__ bf16 g_vht_hi[SEQ * DIM], g_vht_lo[SEQ * DIM];            // [head][e][t]
__device__ bf16 g_ctx_hi[SEQ * DIM], g_ctx_lo[SEQ * DIM];            // [t][head*DHEAD+e]
__device__ bf16 g_f1_hi[SEQ * 2 * DIM], g_f1_lo[SEQ * 2 * DIM];
__device__ bf16 g_at_hi[(size_t)NHEAD * SEQ * SEQ];
__device__ bf16 g_at_lo[(size_t)NHEAD * SEQ * SEQ];

// transposed weights [N][K] bf16 hi/lo
__device__ bf16 g_wqkv_hi[NLAYER * 3 * DIM * DIM], g_wqkv_lo[NLAYER * 3 * DIM * DIM];
__device__ bf16 g_wot_hi[NLAYER * DIM * DIM],  g_wot_lo[NLAYER * DIM * DIM];
__device__ bf16 g_wht_hi[NLAYER * NHEAD * DIM * DHEAD], g_wht_lo[NLAYER * NHEAD * DIM * DHEAD];
__device__ bf16 g_w1t_hi[NLAYER * DIM * 2 * DIM], g_w1t_lo[NLAYER * DIM * 2 * DIM];
__device__ bf16 g_w2t_hi[NLAYER * 2 * DIM * DIM], g_w2t_lo[NLAYER * 2 * DIM * DIM];
__device__ float g_bqkv[NLAYER * 3 * DIM];

// ======================= helpers =======================
__device__ __forceinline__ uint32_t s2u(const void* p) {
    uint32_t a;
    asm("{ .reg .u64 t; cvta.to.shared.u64 t, %1; cvt.u32.u64 %0, t; }" : "=r"(a) : "l"(p));
    return a;
}
__device__ __forceinline__ void split2(float x, bf16& h, bf16& l) {
    h = __float2bfloat16(x);
    l = __float2bfloat16(x - __bfloat162float(h));
}
__device__ __forceinline__ void cp16(uint32_t dst, const void* src) {
    asm volatile("cp.async.cg.shared.global [%0], [%1], 16;" :: "r"(dst), "l"(src) : "memory");
}
#define CP_COMMIT() asm volatile("cp.async.commit_group;" ::: "memory")
#define CP_WAIT(n)  asm volatile("cp.async.wait_group %0;" :: "n"(n) : "memory")

__device__ __forceinline__ void ldm_x4(uint32_t* r, uint32_t addr) {
    asm volatile("ldmatrix.sync.aligned.m8n8.x4.shared.b16 {%0,%1,%2,%3}, [%4];"
                 : "=r"(r[0]), "=r"(r[1]), "=r"(r[2]), "=r"(r[3]) : "r"(addr));
}
__device__ __forceinline__ void mma_bf16(float* c, const uint32_t* a, const uint32_t* b) {
    asm volatile(
        "mma.sync.aligned.m16n8k16.row.col.f32.bf16.bf16.f32 "
        "{%0,%1,%2,%3}, {%4,%5,%6,%7}, {%8,%9}, {%0,%1,%2,%3};"
        : "+f"(c[0]), "+f"(c[1]), "+f"(c[2]), "+f"(c[3])
        : "r"(a[0]), "r"(a[1]), "r"(a[2]), "r"(a[3]), "r"(b[0]), "r"(b[1]));
}

// ======================= split-bf16 mma.sync GEMM =======================
// C[m][n] = alpha * sum_k A[m][k]*B[n][k] + bias[n]   (A,B as hi/lo bf16)
// Tile 128x128, BK=64 bf16, 3-stage cp.async pipeline.
// Batch decomposition: z -> (zo = z/nB, zi = z%nB);
//   A offset = zo*sAo + zi*sAi, B/bias offset = zo*sBo + zi*sBi, C offset = z*sC.
#define GSMEM_BYTES 196608

__global__ void __launch_bounds__(256, 1)
mma_gemm(const bf16* __restrict__ Ahi, const bf16* __restrict__ Alo, int lda, long sAo, long sAi,
         const bf16* __restrict__ Bhi, const bf16* __restrict__ Blo, int ldb, long sBo, long sBi,
         const float* __restrict__ bias, long sBias, int nB,
         float* __restrict__ C, bf16* __restrict__ Chi, bf16* __restrict__ Clo,
         int ldc, long sC, int K, float alpha, int relu)
{
    extern __shared__ char sm[];
    const uint32_t sb = s2u(sm);
    const int tid = threadIdx.x;
    const int wid = tid >> 5;
    const int lane = tid & 31;
    const int wm = wid >> 2;        // 0..1  (M)
    const int wn = wid & 3;         // 0..3  (N)
    const int z = blockIdx.z;
    const int zo = z / nB;
    const int zi = z - zo * nB;
    const long row0 = (long)blockIdx.y * 128;
    const long col0 = (long)blockIdx.x * 128;

    Ahi += zo * sAo + zi * sAi; Alo += zo * sAo + zi * sAi;
    Bhi += zo * sBo + zi * sBi; Blo += zo * sBo + zi * sBi;

    const int nch = K >> 6;

    // ---- async load of one 64-k chunk into a stage buffer ----
    auto load_chunk = [&](int ch, int stage) {
        const long k0 = (long)ch << 6;
#pragma unroll
        for (int i = 0; i < 16; i++) {
            const int u = tid + (i << 8);
            const int t = u >> 10;          // 0=Ahi 1=Alo 2=Bhi 3=Blo
            const int q = u & 1023;         // row*8 + seg
            const long r = q >> 3;
            const int sg = (q & 7) << 3;
            const bf16* p;
            if (t == 0)      p = Ahi + (row0 + r) * lda;
            else if (t == 1) p = Alo + (row0 + r) * lda;
            else if (t == 2) p = Bhi + (col0 + r) * ldb;
            else             p = Blo + (col0 + r) * ldb;
            uint32_t off = (uint32_t)(q << 4);            // row*128 + seg*16
            off ^= (off >> 3) & 0x70;                      // SW128
            cp16(sb + (uint32_t)stage * 65536u + (uint32_t)t * 16384u + off, p + k0 + sg);
        }
        CP_COMMIT();
    };

    float acc[4][4][4];
#pragma unroll
    for (int a = 0; a < 4; a++)
#pragma unroll
        for (int b = 0; b < 4; b++)
#pragma unroll
            for (int c = 0; c < 4; c++) acc[a][b][c] = 0.0f;

    load_chunk(0, 0);
    load_chunk(1, 1);

    for (int ch = 0; ch < nch; ch++) {
        if (ch + 2 < nch) {
            load_chunk(ch + 2, (ch + 2) % 3);
            CP_WAIT(2);
        } else {
            CP_WAIT(0);
        }
        __syncthreads();

        const uint32_t stg = sb + (uint32_t)(ch % 3) * 65536u;

#pragma unroll
        for (int ks = 0; ks < 4; ks++) {
            uint32_t ah[4][4], al[4][4], bh[2][4], bl[2][4];
#pragma unroll
            for (int mt = 0; mt < 4; mt++) {
                const int row = wm * 64 + mt * 16 + (lane & 15);
                const int colb = ks * 32 + ((lane >> 4) << 4);
                uint32_t off = (uint32_t)(row * 128 + colb);
                off ^= (off >> 3) & 0x70;
                ldm_x4(ah[mt], stg + off);
                ldm_x4(al[mt], stg + 16384u + off);
            }
#pragma unroll
            for (int np = 0; np < 2; np++) {
                const int row = wn * 32 + np * 16 + (lane & 7) + ((lane >> 4) << 3);
                const int colb = ks * 32 + (((lane >> 3) & 1) << 4);
                uint32_t off = (uint32_t)(row * 128 + colb);
                off ^= (off >> 3) & 0x70;
                ldm_x4(bh[np], stg + 32768u + off);
                ldm_x4(bl[np], stg + 49152u + off);
            }
#pragma unroll
            for (int mt = 0; mt < 4; mt++)
#pragma unroll
                for (int nt = 0; nt < 4; nt++) {
                    const uint32_t* bhp = &bh[nt >> 1][(nt & 1) * 2];
                    const uint32_t* blp = &bl[nt >> 1][(nt & 1) * 2];
                    mma_bf16(acc[mt][nt], ah[mt], bhp);
                    mma_bf16(acc[mt][nt], ah[mt], blp);
                    mma_bf16(acc[mt][nt], al[mt], bhp);
                }
        }
        __syncthreads();
    }

    // -------- epilogue --------
    float* Cz = C ? C + sC * z : nullptr;
    bf16* Hz = Chi ? Chi + sC * z : nullptr;
    bf16* Lz = Clo ? Clo + sC * z : nullptr;
    const float* bz = bias ? bias + (long)zi * sBias : nullptr;

#pragma unroll
    for (int mt = 0; mt < 4; mt++)
#pragma unroll
        for (int nt = 0; nt < 4; nt++) {
            float* d = acc[mt][nt];
            const long gm = row0 + wm * 64 + mt * 16 + (lane >> 2);
            const long gn = col0 + wn * 32 + nt * 8 + (lane & 3) * 2;
            float b0 = 0.0f, b1 = 0.0f;
            if (bz) { b0 = __ldg(bz + gn); b1 = __ldg(bz + gn + 1); }
#pragma unroll
            for (int half = 0; half < 2; half++) {
                const long r = gm + half * 8;
                float x0 = d[half * 2 + 0] * alpha + b0;
                float x1 = d[half * 2 + 1] * alpha + b1;
                if (relu) { x0 = fmaxf(x0, 0.0f); x1 = fmaxf(x1, 0.0f); }
                const long o = r * ldc + gn;
                if (Cz) *(float2*)(Cz + o) = make_float2(x0, x1);
                if (Hz) {
                    bf16 h0, l0, h1, l1;
                    split2(x0, h0, l0); split2(x1, h1, l1);
                    uint32_t wh = (uint32_t)__bfloat16_as_ushort(h0) |
                                  ((uint32_t)__bfloat16_as_ushort(h1) << 16);
                    uint32_t wl = (uint32_t)__bfloat16_as_ushort(l0) |
                                  ((uint32_t)__bfloat16_as_ushort(l1) << 16);
                    *(uint32_t*)(Hz + o) = wh;
                    *(uint32_t*)(Lz + o) = wl;
                }
            }
        }
}

// ======================= transpose + split: [R][C] f32 -> [C][R] bf16 hi/lo ====
__global__ void __launch_bounds__(256)
transpose_split(const float* __restrict__ in, bf16* __restrict__ ohi, bf16* __restrict__ olo,
                int R, int Ccols, long sIn, long sOut)
{
    __shared__ float t[32][33];
    const float* ip = in + sIn * blockIdx.z;
    const int c0 = blockIdx.x * 32, r0 = blockIdx.y * 32;
    const int tx = threadIdx.x & 31, ty = threadIdx.x >> 5;
#pragma unroll
    for (int j = 0; j < 32; j += 8)
        t[ty + j][tx] = ip[(long)(r0 + ty + j) * Ccols + c0 + tx];
    __syncthreads();
#pragma unroll
    for (int j = 0; j < 32; j += 8) {
        float x = t[tx][ty + j];
        bf16 h, l; split2(x, h, l);
        long o = sOut * blockIdx.z + (long)(c0 + ty + j) * R + r0 + tx;
        ohi[o] = h; olo[o] = l;
    }
}

// ======================= bf16 hi/lo pair transpose: [R][C] -> [C][R] ============
__global__ void __launch_bounds__(256)
transpose_pair(const bf16* __restrict__ ihi, const bf16* __restrict__ ilo,
               bf16* __restrict__ ohi, bf16* __restrict__ olo,
               int R, int Ccols, long sIn, long sOut)
{
    __shared__ unsigned short t[32][33];
    const int c0 = blockIdx.x * 32, r0 = blockIdx.y * 32;
    const int tx = threadIdx.x & 31, ty = threadIdx.x >> 5;
    const bf16* a = ihi + sIn * blockIdx.z;
    bf16* o = ohi + sOut * blockIdx.z;
#pragma unroll
    for (int pass = 0; pass < 2; pass++) {
#pragma unroll
        for (int j = 0; j < 32; j += 8)
            t[ty + j][tx] = __bfloat16_as_ushort(a[(long)(r0 + ty + j) * Ccols + c0 + tx]);
        __syncthreads();
#pragma unroll
        for (int j = 0; j < 32; j += 8)
            o[(long)(c0 + ty + j) * R + r0 + tx] = __ushort_as_bfloat16(t[tx][ty + j]);
        __syncthreads();
        a = ilo + sIn * blockIdx.z;
        o = olo + sOut * blockIdx.z;
    }
}

// ======================= bias concat: bq|bk|bv -> [L][3][D] =====================
__global__ void __launch_bounds__(256)
concat_bias(const float* __restrict__ bq, const float* __restrict__ bk,
            const float* __restrict__ bv, float* __restrict__ out)
{
    const int idx = blockIdx.x * blockDim.x + threadIdx.x;
    if (idx >= NLAYER * 3 * DIM) return;
    const int l = idx / (3 * DIM);
    const int w = (idx / DIM) % 3;
    const int i = idx % DIM;
    const float* src = (w == 0) ? bq : (w == 1) ? bk : bv;
    out[idx] = src[l * DIM + i];
}

// ======================= copy + split =======================
__global__ void __launch_bounds__(256)
copy_split(const float* __restrict__ src, float* __restrict__ dst,
           bf16* __restrict__ dhi, bf16* __restrict__ dlo, int n)
{
    const int i = blockIdx.x * blockDim.x + threadIdx.x;
    if (i < n) {
        float v = src[i];
        dst[i] = v;
        bf16 h, l; split2(v, h, l);
        dhi[i] = h; dlo[i] = l;
    }
}

// ======================= softmax (f32 in, bf16 hi/lo out) =======================
__global__ void __launch_bounds__(256)
softmax_kernel(const float* __restrict__ scores, bf16* __restrict__ ohi, bf16* __restrict__ olo)
{
    const size_t base = (size_t)blockIdx.x * SEQ;
    const float* p = scores + base;
    const int tid = threadIdx.x;

    float v[12];
    float mx = -1e30f;
#pragma unroll
    for (int i = 0; i < 12; i++) {
        v[i] = p[tid + i * 256];
        mx = fmaxf(mx, v[i]);
    }
    __shared__ float red[256];
    red[tid] = mx;
    __syncthreads();
    for (int s = 128; s > 0; s >>= 1) {
        if (tid < s) red[tid] = fmaxf(red[tid], red[tid + s]);
        __syncthreads();
    }
    mx = red[0];
    __syncthreads();

    float sum = 0.0f;
#pragma unroll
    for (int i = 0; i < 12; i++) {
        v[i] = __expf(v[i] - mx);
        sum += v[i];
    }
    red[tid] = sum;
    __syncthreads();
    for (int s = 128; s > 0; s >>= 1) {
        if (tid < s) red[tid] += red[tid + s];
        __syncthreads();
    }
    const float inv = 1.0f / red[0];
#pragma unroll
    for (int i = 0; i < 12; i++) {
        float x = v[i] * inv;
        bf16 h, l; split2(x, h, l);
        ohi[base + tid + i * 256] = h;
        olo[base + tid + i * 256] = l;
    }
}

// ======================= add + layernorm (emit f32 + hi/lo) ====================
__global__ void __launch_bounds__(256)
add_ln_kernel(float* __restrict__ h, const float* __restrict__ x,
              const float* __restrict__ g, const float* __restrict__ b,
              bf16* __restrict__ ohi, bf16* __restrict__ olo)
{
    const long row = blockIdx.x;
    float* hp = h + row * (long)DIM;
    const float* xp = x + row * (long)DIM;
    const int tid = threadIdx.x;

    float v[4];
    float sum = 0.0f;
#pragma unroll
    for (int i = 0; i < 4; i++) {
        const int c = tid + i * 256;
        v[i] = hp[c] + xp[c];
        sum += v[i];
    }
    __shared__ float red[256];
    red[tid] = sum;
    __syncthreads();
    for (int s = 128; s > 0; s >>= 1) {
        if (tid < s) red[tid] += red[tid + s];
        __syncthreads();
    }
    const float mu = red[0] * (1.0f / DIM);
    __syncthreads();

    float vs = 0.0f;
#pragma unroll
    for (int i = 0; i < 4; i++) {
        const float d = v[i] - mu;
        vs += d * d;
    }
    red[tid] = vs;
    __syncthreads();
    for (int s = 128; s > 0; s >>= 1) {
        if (tid < s) red[tid] += red[tid + s];
        __syncthreads();
    }
    const float inv = rsqrtf(red[0] * (1.0f / DIM) + LN_EPS);
    __syncthreads();
#pragma unroll
    for (int i = 0; i < 4; i++) {
        const int c = tid + i * 256;
        float y = g[c] * (v[i] - mu) * inv + b[c];
        hp[c] = y;
        bf16 hh, ll; split2(y, hh, ll);
        ohi[row * (long)DIM + c] = hh;
        olo[row * (long)DIM + c] = ll;
    }
}

// ======================= output heads =======================
__global__ void __launch_bounds__(256)
heads_kernel(const float* __restrict__ h, const float* __restrict__ Whead,
             const float* __restrict__ bhead, const int* __restrict__ nev,
             const int* __restrict__ nag, float* __restrict__ out, int total)
{
    const int warpId = (blockIdx.x * blockDim.x + threadIdx.x) >> 5;
    const int lane = threadIdx.x & 31;
    if (warpId >= total) return;
    const int NEv = *nev;
    const int NAg = *nag;
    int headIdx, token;
    if (warpId < 3 * NAg) {
        headIdx = warpId / NAg;
        token = NEv + warpId % NAg;
    } else {
        headIdx = 3;
        token = warpId - 3 * NAg;
    }
    const float* hr = h + (long)token * DIM;
    const float* w = Whead + (long)headIdx * DIM;
    float s = 0.0f;
    for (int i = lane; i < DIM; i += 32) s = fmaf(hr[i], w[i], s);
#pragma unroll
    for (int off = 16; off > 0; off >>= 1) s += __shfl_down_sync(0xFFFFFFFFu, s, off);
    if (lane == 0) out[warpId] = s + bhead[headIdx];
}

// ======================= host orchestration =======================
static void tcg(const bf16* Ahi, const bf16* Alo, int lda, long sAo, long sAi,
                const bf16* Bhi, const bf16* Blo, int ldb, long sBo, long sBi,
                const float* bias, long sBias, int nB,
                float* C, bf16* Chi, bf16* Clo, int ldc, long sC,
                int M, int N, int K, int batch, float alpha, int relu)
{
    dim3 grid(N / 128, M / 128, batch);
    mma_gemm<<<grid, 256, GSMEM_BYTES>>>(Ahi, Alo, lda, sAo, sAi, Bhi, Blo, ldb, sBo, sBi,
                                         bias, sBias, nB, C, Chi, Clo, ldc, sC, K, alpha, relu);
}

#define SYM(var, name) cudaGetSymbolAddress((void**)&var, name)

extern "C" void kernel_launch(void* const* d_in, const int* in_sizes, int n_in,
                              void* d_out, int out_size)
{
    const float* hidden = (const float*)d_in[0];
    const float* Wq = (const float*)d_in[1];
    const float* bq = (const float*)d_in[2];
    const float* Wk = (const float*)d_in[3];
    const float* bk = (const float*)d_in[4];
    const float* Wv = (const float*)d_in[5];
    const float* bv = (const float*)d_in[6];
    const float* Wh = (const float*)d_in[7];
    const float* bh = (const float*)d_in[8];
    const float* Wo = (const float*)d_in[9];
    const float* bo = (const float*)d_in[10];
    const float* g1 = (const float*)d_in[11];
    const float* b1n = (const float*)d_in[12];
    const float* g2 = (const float*)d_in[13];
    const float* b2n = (const float*)d_in[14];
    const float* Wf1 = (const float*)d_in[15];
    const float* bf1 = (const float*)d_in[16];
    const float* Wf2 = (const float*)d_in[17];
    const float* bf2 = (const float*)d_in[18];
    const float* Whead = (const float*)d_in[19];
    const float* bhead = (const float*)d_in[20];
    const int* n_events = (const int*)d_in[21];
    const int* n_agents = (const int*)d_in[22];
    (void)in_sizes; (void)n_in;

    cudaFuncSetAttribute(mma_gemm, cudaFuncAttributeMaxDynamicSharedMemorySize, GSMEM_BYTES);

    float *h, *tmp, *scores, *bqkv;
    SYM(h, g_h); SYM(tmp, g_tmp); SYM(scores, g_scores); SYM(bqkv, g_bqkv);
    bf16 *h_hi, *h_lo, *qkv_hi, *qkv_lo, *qkvh_hi, *qkvh_lo;
    bf16 *vht_hi, *vht_lo, *ctx_hi, *ctx_lo, *f1_hi, *f1_lo, *at_hi, *at_lo;
    SYM(h_hi, g_h_hi); SYM(h_lo, g_h_lo);
    SYM(qkv_hi, g_qkv_hi); SYM(qkv_lo, g_qkv_lo);
    SYM(qkvh_hi, g_qkvh_hi); SYM(qkvh_lo, g_qkvh_lo);
    SYM(vht_hi, g_vht_hi); SYM(vht_lo, g_vht_lo);
    SYM(ctx_hi, g_ctx_hi); SYM(ctx_lo, g_ctx_lo);
    SYM(f1_hi, g_f1_hi); SYM(f1_lo, g_f1_lo);
    SYM(at_hi, g_at_hi); SYM(at_lo, g_at_lo);
    bf16 *wqkv_hi, *wqkv_lo, *wot_hi, *wot_lo, *wht_hi, *wht_lo;
    bf16 *w1t_hi, *w1t_lo, *w2t_hi, *w2t_lo;
    SYM(wqkv_hi, g_wqkv_hi); SYM(wqkv_lo, g_wqkv_lo);
    SYM(wot_hi, g_wot_hi); SYM(wot_lo, g_wot_lo);
    SYM(wht_hi, g_wht_hi); SYM(wht_lo, g_wht_lo);
    SYM(w1t_hi, g_w1t_hi); SYM(w1t_lo, g_w1t_lo);
    SYM(w2t_hi, g_w2t_hi); SYM(w2t_lo, g_w2t_lo);

    const long DD = (long)DIM * DIM;
    const long SD = (long)SEQ * DIM;
    const long SS = (long)SEQ * SEQ;
    const long SDh = (long)SEQ * DHEAD;
    const long WHL = (long)NHEAD * DIM * DHEAD;

    // ---- weight transposes into combined layouts ----
    transpose_split<<<dim3(DIM / 32, DIM / 32, NLAYER), 256>>>(Wq, wqkv_hi, wqkv_lo, DIM, DIM, DD, 3 * DD);
    transpose_split<<<dim3(DIM / 32, DIM / 32, NLAYER), 256>>>(Wk, wqkv_hi + DD, wqkv_lo + DD, DIM, DIM, DD, 3 * DD);
    transpose_split<<<dim3(DIM / 32, DIM / 32, NLAYER), 256>>>(Wv, wqkv_hi + 2 * DD, wqkv_lo + 2 * DD, DIM, DIM, DD, 3 * DD);
    transpose_split<<<dim3(DIM / 32, DIM / 32, NLAYER), 256>>>(Wo, wot_hi, wot_lo, DIM, DIM, DD, DD);
    transpose_split<<<dim3(DHEAD / 32, DIM / 32, NLAYER * NHEAD), 256>>>(
        Wh, wht_hi, wht_lo, DIM, DHEAD, (long)DIM * DHEAD, (long)DIM * DHEAD);
    transpose_split<<<dim3(2 * DIM / 32, DIM / 32, NLAYER), 256>>>(Wf1, w1t_hi, w1t_lo, DIM, 2 * DIM, 2 * DD, 2 * DD);
    transpose_split<<<dim3(DIM / 32, 2 * DIM / 32, NLAYER), 256>>>(Wf2, w2t_hi, w2t_lo, 2 * DIM, DIM, 2 * DD, 2 * DD);
    concat_bias<<<(NLAYER * 3 * DIM + 255) / 256, 256>>>(bq, bk, bv, bqkv);

    const int n = SEQ * DIM;
    copy_split<<<(n + 255) / 256, 256>>>(hidden, h, h_hi, h_lo, n);

    const float attn_scale = 1.0f / 16.0f;

    for (int l = 0; l < NLAYER; l++) {
        // QKV projections, one launch (z: 0=Q 1=K 2=V)
        tcg(h_hi, h_lo, DIM, 0, 0,
            wqkv_hi + l * 3 * DD, wqkv_lo + l * 3 * DD, DIM, 0, DD,
            bqkv + (long)l * 3 * DIM, DIM, 3,
            nullptr, qkv_hi, qkv_lo, DIM, SD, SEQ, DIM, DIM, 3, 1.0f, 0);
        // per-head projections, one launch (z = which*4 + head)
        tcg(qkv_hi, qkv_lo, DIM, SD, 0,
            wht_hi + l * WHL, wht_lo + l * WHL, DIM, 0, (long)DIM * DHEAD,
            bh + (long)l * NHEAD * DHEAD, DHEAD, NHEAD,
            nullptr, qkvh_hi, qkvh_lo, DHEAD, SDh, SEQ, DHEAD, DIM, 3 * NHEAD, 1.0f, 0);
        // Vh [head][t][e] -> [head][e][t] (hi and lo transposed independently)
        transpose_pair<<<dim3(DHEAD / 32, SEQ / 32, NHEAD), 256>>>(
            qkvh_hi + 2 * SD, qkvh_lo + 2 * SD, vht_hi, vht_lo, SEQ, DHEAD, SDh, SDh);
        // scores = scale * Qh @ Kh^T
        tcg(qkvh_hi, qkvh_lo, DHEAD, SDh, 0,
            qkvh_hi + SD, qkvh_lo + SD, DHEAD, SDh, 0,
            nullptr, 0, 1,
            scores, nullptr, nullptr, SEQ, SS, SEQ, SEQ, DHEAD, NHEAD, attn_scale, 0);
        // softmax -> attn hi/lo
        softmax_kernel<<<NHEAD * SEQ, 256>>>(scores, at_hi, at_lo);
        // ctx = attn @ Vh -> [t][head*DHEAD+e]
        tcg(at_hi, at_lo, SEQ, SS, 0,
            vht_hi, vht_lo, SEQ, SDh, 0,
            nullptr, 0, 1,
            nullptr, ctx_hi, ctx_lo, DIM, DHEAD, SEQ, DHEAD, SEQ, NHEAD, 1.0f, 0);
        // attn_out = ctx @ Wo + bo -> f32 tmp
        tcg(ctx_hi, ctx_lo, DIM, 0, 0,
            wot_hi + l * DD, wot_lo + l * DD, DIM, 0, 0,
            bo + (long)l * DIM, 0, 1,
            tmp, nullptr, nullptr, DIM, 0, SEQ, DIM, DIM, 1, 1.0f, 0);
        add_ln_kernel<<<SEQ, 256>>>(h, tmp, g1 + (long)l * DIM, b1n + (long)l * DIM, h_hi, h_lo);
        // FFN
        tcg(h_hi, h_lo, DIM, 0, 0,
            w1t_hi + l * 2 * DD, w1t_lo + l * 2 * DD, DIM, 0, 0,
            bf1 + (long)l * 2 * DIM, 0, 1,
            nullptr, f1_hi, f1_lo, 2 * DIM, 0, SEQ, 2 * DIM, DIM, 1, 1.0f, 1);
        tcg(f1_hi, f1_lo, 2 * DIM, 0, 0,
            w2t_hi + l * 2 * DD, w2t_lo + l * 2 * DD, 2 * DIM, 0, 0,
            bf2 + (long)l * DIM, 0, 1,
            tmp, nullptr, nullptr, DIM, 0, SEQ, DIM, 2 * DIM, 1, 1.0f, 0);
        add_ln_kernel<<<SEQ, 256>>>(h, tmp, g2 + (long)l * DIM, b2n + (long)l * DIM, h_hi, h_lo);
    }

    const int blocks = (out_size * 32 + 255) / 256;
    heads_kernel<<<blocks, 256>>>(h, Whead, bhead, n_events, n_agents, (float*)d_out, out_size);
}